// round 1
// baseline (speedup 1.0000x reference)
#include <cuda_runtime.h>

// Problem constants
#define NB 4
#define NS 2048
#define NF 512
#define NH 8
#define ND 32
#define HID 256
#define ACTF 16
#define ROWS (NB*NS)          // 8192
#define NP1 896               // padded x-proj output width (784 real -> 7*128)
#define NPU 520               // action proj width: 256 ku + 256 vu + 8 gamma
#define NC 32                 // chunks per sequence
#define CHUNK 64              // NS / NC
#define EPSF 1e-6f

// ---------------- scratch (static device globals; no allocations) ----------
__device__ float g_Wcat[NF*NP1];
__device__ float g_proj[ROWS*NP1];
__device__ float g_Wucat[ACTF*NPU];
__device__ float g_projU[ROWS*NPU];
__device__ float g_qn[ROWS*HID];
__device__ float g_kn[ROWS*HID];
__device__ float g_kun[ROWS*HID];
__device__ float g_vs[ROWS*HID];
__device__ float g_vu[ROWS*HID];
__device__ float g_sc[ROWS*NH*4];        // beta, Aeff, Bg, ku.k
__device__ float g_u[ROWS*HID];
__device__ float g_w[ROWS*HID];
__device__ float g_cum[32*NC*ND*ND];
__device__ float g_loc[32*NC*ND*ND];
__device__ float g_hinit[32*NC*ND*ND];
__device__ float g_out[ROWS*HID];

__device__ __forceinline__ float sigm(float z) { return 1.f / (1.f + __expf(-z)); }

// ---------------- 1. weight concat (pad to NP1 with zeros) -----------------
__global__ void prep_weights(const float* __restrict__ Wq, const float* __restrict__ Wk,
                             const float* __restrict__ Wv, const float* __restrict__ Wb,
                             const float* __restrict__ Wa, const float* __restrict__ Wku,
                             const float* __restrict__ Wvu, const float* __restrict__ Wg) {
    int i = blockIdx.x * blockDim.x + threadIdx.x;
    const int n1 = NF * NP1;
    if (i < n1) {
        int r = i / NP1, c = i - r * NP1;
        float v = 0.f;
        if (c < 256)       v = Wq[r*256 + c];
        else if (c < 512)  v = Wk[r*256 + c - 256];
        else if (c < 768)  v = Wv[r*256 + c - 512];
        else if (c < 776)  v = Wb[r*8 + c - 768];
        else if (c < 784)  v = Wa[r*8 + c - 776];
        g_Wcat[i] = v;
    } else {
        int j = i - n1;
        if (j < ACTF * NPU) {
            int r = j / NPU, c = j - r * NPU;
            float v;
            if (c < 256)      v = Wku[r*256 + c];
            else if (c < 512) v = Wvu[r*256 + c - 256];
            else              v = Wg[r*8 + c - 512];
            g_Wucat[j] = v;
        }
    }
}

// ---------------- 2. tiled fp32 SGEMM (128x128x8, 8x8 per thread) ----------
__device__ __forceinline__ void sgemm_body(const float* __restrict__ A,
                                           const float* __restrict__ Bm,
                                           float* __restrict__ C,
                                           int N, int K,
                                           const float* __restrict__ bias) {
    const int BM = 128, BN = 128, BK = 8, TM = 8, TN = 8;
    __shared__ float As[BK][BM];
    __shared__ float Bs[BK][BN];
    int tid = threadIdx.x;
    const float* Ab = A + (size_t)blockIdx.y * BM * K;
    const float* Bb = Bm + blockIdx.x * BN;
    float* Cb = C + (size_t)blockIdx.y * BM * N + blockIdx.x * BN;
    int irA = tid >> 1, icA = (tid & 1) * 4;
    int irB = tid >> 5, icB = (tid & 31) * 4;
    int tRow = (tid >> 4) * TM, tCol = (tid & 15) * TN;
    float acc[TM][TN];
#pragma unroll
    for (int m = 0; m < TM; m++)
#pragma unroll
        for (int n = 0; n < TN; n++) acc[m][n] = 0.f;

    for (int k0 = 0; k0 < K; k0 += BK) {
        float4 a4 = *(const float4*)(Ab + (size_t)irA * K + icA);
        As[icA + 0][irA] = a4.x; As[icA + 1][irA] = a4.y;
        As[icA + 2][irA] = a4.z; As[icA + 3][irA] = a4.w;
        *(float4*)(&Bs[irB][icB]) = *(const float4*)(Bb + (size_t)irB * N + icB);
        __syncthreads();
#pragma unroll
        for (int kk = 0; kk < BK; kk++) {
            float rA[TM], rB[TN];
#pragma unroll
            for (int m = 0; m < TM; m++) rA[m] = As[kk][tRow + m];
#pragma unroll
            for (int n = 0; n < TN; n++) rB[n] = Bs[kk][tCol + n];
#pragma unroll
            for (int m = 0; m < TM; m++)
#pragma unroll
                for (int n = 0; n < TN; n++) acc[m][n] += rA[m] * rB[n];
        }
        __syncthreads();
        Ab += BK; Bb += (size_t)BK * N;
    }
#pragma unroll
    for (int m = 0; m < TM; m++) {
#pragma unroll
        for (int n0 = 0; n0 < TN; n0 += 4) {
            float4 v;
            v.x = acc[m][n0 + 0]; v.y = acc[m][n0 + 1];
            v.z = acc[m][n0 + 2]; v.w = acc[m][n0 + 3];
            if (bias) {
                const float* bp = bias + blockIdx.x * BN + tCol + n0;
                v.x += bp[0]; v.y += bp[1]; v.z += bp[2]; v.w += bp[3];
            }
            *(float4*)(&Cb[(size_t)(tRow + m) * N + tCol + n0]) = v;
        }
    }
}

__global__ __launch_bounds__(256) void sgemm_xproj(const float* __restrict__ x) {
    sgemm_body(x, g_Wcat, g_proj, NP1, NF, nullptr);
}
__global__ __launch_bounds__(256) void sgemm_yout(const float* __restrict__ Wout,
                                                  const float* __restrict__ bout,
                                                  float* __restrict__ y) {
    sgemm_body(g_out, Wout, y, NF, HID, bout);
}

// ---------------- 3. action projection (K=16, tiny) ------------------------
__global__ __launch_bounds__(256) void action_proj(const float* __restrict__ act) {
    __shared__ float a[ACTF];
    int row = blockIdx.x;
    if (threadIdx.x < ACTF) a[threadIdx.x] = act[row * ACTF + threadIdx.x];
    __syncthreads();
    for (int c = threadIdx.x; c < NPU; c += blockDim.x) {
        float s = 0.f;
#pragma unroll
        for (int k = 0; k < ACTF; k++) s += a[k] * g_Wucat[k * NPU + c];
        g_projU[row * NPU + c] = s;
    }
}

// ---------------- 4. activations + l2norm + per-step scalars ----------------
__global__ __launch_bounds__(256) void act_kernel(const float* __restrict__ mask) {
    int w = (blockIdx.x * blockDim.x + threadIdx.x) >> 5;   // (b*S+s)*H + h
    int lane = threadIdx.x & 31;
    if (w >= ROWS * NH) return;
    int bs = w >> 3, h = w & 7;
    int pb = bs * NP1;
    float qr  = g_proj[pb + h*32 + lane];
    float kr  = g_proj[pb + 256 + h*32 + lane];
    float vr  = g_proj[pb + 512 + h*32 + lane];
    float kur = g_projU[bs*NPU + h*32 + lane];
    float vur = g_projU[bs*NPU + 256 + h*32 + lane];

    float q  = qr * sigm(qr);
    float k  = kr * sigm(kr);
    float ku = kur * sigm(kur);

    float sq = q*q, sk = k*k, sku = ku*ku;
#pragma unroll
    for (int o = 16; o > 0; o >>= 1) {
        sq  += __shfl_xor_sync(0xffffffffu, sq,  o);
        sk  += __shfl_xor_sync(0xffffffffu, sk,  o);
        sku += __shfl_xor_sync(0xffffffffu, sku, o);
    }
    q  *= rsqrtf(sq  + EPSF);
    k  *= rsqrtf(sk  + EPSF);
    ku *= rsqrtf(sku + EPSF);

    float dk = ku * k;
#pragma unroll
    for (int o = 16; o > 0; o >>= 1) dk += __shfl_xor_sync(0xffffffffu, dk, o);

    int base = w * 32;
    g_qn[base + lane]  = q;
    g_kn[base + lane]  = k;
    g_kun[base + lane] = ku;
    g_vs[base + lane]  = vr;
    g_vu[base + lane]  = vur;
    if (lane == 0) {
        float br = g_proj[pb + 768 + h];
        float ar = g_proj[pb + 776 + h];
        float gr = g_projU[bs*NPU + 512 + h];
        float m  = mask[bs];
        g_sc[w*4 + 0] = sigm(br);                 // beta
        g_sc[w*4 + 1] = sigm(ar) * (1.f - m);     // Aeff
        g_sc[w*4 + 2] = sigm(gr);                 // Bg
        g_sc[w*4 + 3] = dk;                       // ku . k
    }
}

// ---------------- 5. phase 1: chunked scan (warp per chain-chunk) ----------
// decay = Aeff*(I - beta k k^T); H_t = Aeff*H + c k^T + d ku^T
// c_i = beta*vs_i - Aeff*beta*(Hk)_i - Bg*beta*(ku.k)*vu_i ;  d_i = Bg*vu_i
__global__ __launch_bounds__(128) void phase1() {
    int wg = blockIdx.x * 4 + (threadIdx.x >> 5);   // 0..1023
    int lane = threadIdx.x & 31;
    int chain = wg >> 5;        // b*8+h
    int c = wg & 31;
    int b = chain >> 3, h = chain & 7;

    float cum[32], hl[32];
#pragma unroll
    for (int j = 0; j < 32; j++) { cum[j] = (j == lane) ? 1.f : 0.f; hl[j] = 0.f; }

    int t0 = c * CHUNK;
    for (int t = t0; t < t0 + CHUNK; t++) {
        int w = (b * NS + t) * NH + h;
        int base = w * 32;
        float kreg  = g_kn[base + lane];
        float qreg  = g_qn[base + lane];
        float kureg = g_kun[base + lane];
        float vs = g_vs[base + lane];
        float vu = g_vu[base + lane];
        float beta = g_sc[w*4 + 0];
        float Ae   = g_sc[w*4 + 1];
        float Bg   = g_sc[w*4 + 2];
        float kuk  = g_sc[w*4 + 3];

        float ck = 0.f, hk = 0.f;
#pragma unroll
        for (int j = 0; j < 32; j++) {
            float kj = __shfl_sync(0xffffffffu, kreg, j);
            ck += cum[j] * kj;
            hk += hl[j]  * kj;
        }
        float e  = Ae * beta * ck;
        float cc = beta * vs - Ae * beta * hk - Bg * beta * kuk * vu;
        float dd = Bg * vu;

        float u = 0.f, wv = 0.f;
#pragma unroll
        for (int j = 0; j < 32; j++) {
            float kj  = __shfl_sync(0xffffffffu, kreg,  j);
            float kuj = __shfl_sync(0xffffffffu, kureg, j);
            float qj  = __shfl_sync(0xffffffffu, qreg,  j);
            cum[j] = Ae * cum[j] - e * kj;
            hl[j]  = Ae * hl[j] + cc * kj + dd * kuj;
            u  += cum[j] * qj;
            wv += hl[j]  * qj;
        }
        g_u[base + lane] = u;
        g_w[base + lane] = wv;
    }
    int mb = (chain * NC + c) * 1024 + lane * 32;
#pragma unroll
    for (int j = 0; j < 32; j += 4) {
        *(float4*)&g_cum[mb + j] = make_float4(cum[j], cum[j+1], cum[j+2], cum[j+3]);
        *(float4*)&g_loc[mb + j] = make_float4(hl[j],  hl[j+1],  hl[j+2],  hl[j+3]);
    }
}

// ---------------- 6. phase 2: fold chunks (32 blocks, 32x32 matmuls) --------
__global__ __launch_bounds__(1024) void phase2(const float* __restrict__ carry,
                                               float* __restrict__ outCarry) {
    int chain = blockIdx.x;
    int i = threadIdx.x >> 5, j = threadIdx.x & 31;
    float hreg = carry[chain * 1024 + i * 32 + j];
    for (int c = 0; c < NC; c++) {
        int mb = (chain * NC + c) * 1024;
        g_hinit[mb + i * 32 + j] = hreg;       // state at chunk start
        float nv = g_loc[mb + i * 32 + j];
#pragma unroll
        for (int m = 0; m < 32; m++)
            nv += __shfl_sync(0xffffffffu, hreg, m) * g_cum[mb + m * 32 + j];
        hreg = nv;
    }
    outCarry[chain * 1024 + i * 32 + j] = hreg;  // new_carry
}

// ---------------- 7. phase 3: out_t = Hinit @ u_t + w_t ---------------------
__global__ __launch_bounds__(256) void phase3() {
    __shared__ float sh[32 * 33];
    int blk = blockIdx.x;            // chain*NC + c
    int chain = blk >> 5, c = blk & 31;
    int b = chain >> 3, h = chain & 7;
    int mb = blk * 1024;
    for (int idx = threadIdx.x; idx < 1024; idx += 256)
        sh[(idx >> 5) * 33 + (idx & 31)] = g_hinit[mb + idx];
    __syncthreads();
    int warp = threadIdx.x >> 5, lane = threadIdx.x & 31;
    for (int it = 0; it < 8; it++) {
        int t = c * CHUNK + it * 8 + warp;
        int w = (b * NS + t) * NH + h;
        int base = w * 32;
        float ul  = g_u[base + lane];
        float acc = g_w[base + lane];
#pragma unroll
        for (int j = 0; j < 32; j++)
            acc += sh[lane * 33 + j] * __shfl_sync(0xffffffffu, ul, j);
        g_out[(b * NS + t) * HID + h * 32 + lane] = acc;
    }
}

// ---------------- 8. RMS norm over 256 + scale ------------------------------
__global__ __launch_bounds__(256) void rms_kernel(const float* __restrict__ scale) {
    __shared__ float red[8];
    int bs = blockIdx.x;
    float v = g_out[bs * HID + threadIdx.x];
    float ss = v * v;
#pragma unroll
    for (int o = 16; o > 0; o >>= 1) ss += __shfl_xor_sync(0xffffffffu, ss, o);
    if ((threadIdx.x & 31) == 0) red[threadIdx.x >> 5] = ss;
    __syncthreads();
    float tot = 0.f;
#pragma unroll
    for (int r = 0; r < 8; r++) tot += red[r];
    float inv = rsqrtf(tot * (1.f / 256.f) + EPSF);
    g_out[bs * HID + threadIdx.x] = v * inv * scale[threadIdx.x];
}

// ---------------- launcher ---------------------------------------------------
extern "C" void kernel_launch(void* const* d_in, const int* in_sizes, int n_in,
                              void* d_out, int out_size) {
    const float* x      = (const float*)d_in[0];
    const float* action = (const float*)d_in[1];
    const float* mask   = (const float*)d_in[2];
    const float* carry  = (const float*)d_in[3];
    const float* Wq     = (const float*)d_in[4];
    const float* Wk     = (const float*)d_in[5];
    const float* Wv     = (const float*)d_in[6];
    const float* Wbeta  = (const float*)d_in[7];
    const float* Walpha = (const float*)d_in[8];
    const float* Wku    = (const float*)d_in[9];
    const float* Wvu    = (const float*)d_in[10];
    const float* Wgamma = (const float*)d_in[11];
    const float* rmssc  = (const float*)d_in[12];
    const float* Wout   = (const float*)d_in[13];
    const float* bout   = (const float*)d_in[14];

    float* outCarry = (float*)d_out;                       // (B,H,D,D) = 32768
    float* y        = (float*)d_out + NB * NH * ND * ND;   // (B,S,F)

    int nprep = NF * NP1 + ACTF * NPU;
    prep_weights<<<(nprep + 255) / 256, 256>>>(Wq, Wk, Wv, Wbeta, Walpha, Wku, Wvu, Wgamma);

    dim3 g1(NP1 / 128, ROWS / 128);       // (7, 64)
    sgemm_xproj<<<g1, 256>>>(x);

    action_proj<<<ROWS, 256>>>(action);
    act_kernel<<<(ROWS * NH * 32) / 256, 256>>>(mask);

    phase1<<<256, 128>>>();
    phase2<<<32, 1024>>>(carry, outCarry);
    phase3<<<1024, 256>>>();
    rms_kernel<<<ROWS, 256>>>(rmssc);

    dim3 g2(NF / 128, ROWS / 128);        // (4, 64)
    sgemm_yout<<<g2, 256>>>(Wout, bout, y);
}

// round 3
// speedup vs baseline: 1.5406x; 1.5406x over previous
#include <cuda_runtime.h>
#include <cuda_bf16.h>
#include <cstdint>

// Problem constants
#define NB 4
#define NS 2048
#define NF 512
#define NH 8
#define ND 32
#define HID 256
#define ACTF 16
#define ROWS (NB*NS)          // 8192
#define NP1 896               // padded x-proj output width
#define NPU 520               // action proj width: 256 ku + 256 vu + 8 gamma
#define NC 32                 // chunks per sequence
#define CHUNK 64              // NS / NC
#define EPSF 1e-6f

// ---------------- scratch (static device globals; no allocations) ----------
__device__ __nv_bfloat16 g_Bt1h[NP1*NF];   // [896,512] W1^T hi
__device__ __nv_bfloat16 g_Bt1l[NP1*NF];
__device__ __nv_bfloat16 g_Bt2h[NF*HID];   // [512,256] Wout^T hi
__device__ __nv_bfloat16 g_Bt2l[NF*HID];
__device__ float g_proj[ROWS*NP1];
__device__ float g_Wucat[ACTF*NPU];
__device__ float g_projU[ROWS*NPU];
__device__ float g_qn[ROWS*HID];
__device__ float g_kn[ROWS*HID];
__device__ float g_kun[ROWS*HID];
__device__ float g_vs[ROWS*HID];
__device__ float g_vu[ROWS*HID];
__device__ float g_sc[ROWS*NH*4];        // beta, Aeff, Bg, ku.k
__device__ float g_u[ROWS*HID];
__device__ float g_w[ROWS*HID];
__device__ float g_cum[32*NC*ND*ND];
__device__ float g_loc[32*NC*ND*ND];
__device__ float g_hinit[32*NC*ND*ND];
__device__ float g_out[ROWS*HID];

__device__ __forceinline__ float sigm(float z) { return 1.f / (1.f + __expf(-z)); }

__device__ __forceinline__ uint32_t smem_to_u32(const void* smem_ptr) {
    uint32_t addr;
    asm("{ .reg .u64 tmp; cvta.to.shared.u64 tmp, %1; cvt.u32.u64 %0, tmp; }"
        : "=r"(addr) : "l"(smem_ptr));
    return addr;
}
__device__ __forceinline__ void ldsm_x4(uint32_t* r, uint32_t addr) {
    asm volatile("ldmatrix.sync.aligned.m8n8.x4.shared.b16 {%0,%1,%2,%3}, [%4];"
        : "=r"(r[0]), "=r"(r[1]), "=r"(r[2]), "=r"(r[3]) : "r"(addr));
}
__device__ __forceinline__ void mma16816(float* d, const uint32_t* a, const uint32_t* b) {
    asm volatile(
        "mma.sync.aligned.m16n8k16.row.col.f32.bf16.bf16.f32 "
        "{%0,%1,%2,%3}, {%4,%5,%6,%7}, {%8,%9}, {%0,%1,%2,%3};"
        : "+f"(d[0]), "+f"(d[1]), "+f"(d[2]), "+f"(d[3])
        : "r"(a[0]), "r"(a[1]), "r"(a[2]), "r"(a[3]), "r"(b[0]), "r"(b[1]));
}
__device__ __forceinline__ uint32_t pack_bf16(float x, float y) {
    __nv_bfloat16 hx = __float2bfloat16(x), hy = __float2bfloat16(y);
    return ((uint32_t)__bfloat16_as_ushort(hy) << 16) | __bfloat16_as_ushort(hx);
}

// ---------------- 1. weight prep: split-bf16 transposed weights ------------
#define N1ELEM (NP1*NF)
#define N2ELEM (NF*HID)
__global__ void prep_weights(const float* __restrict__ Wq, const float* __restrict__ Wk,
                             const float* __restrict__ Wv, const float* __restrict__ Wb,
                             const float* __restrict__ Wa, const float* __restrict__ Wku,
                             const float* __restrict__ Wvu, const float* __restrict__ Wg,
                             const float* __restrict__ Wout) {
    int i = blockIdx.x * blockDim.x + threadIdx.x;
    if (i < N1ELEM) {
        int n = i >> 9, k = i & 511;          // Bt1[n,k] = W1[k,n]
        float v = 0.f;
        if (n < 256)       v = Wq[k*256 + n];
        else if (n < 512)  v = Wk[k*256 + n - 256];
        else if (n < 768)  v = Wv[k*256 + n - 512];
        else if (n < 776)  v = Wb[k*8 + n - 768];
        else if (n < 784)  v = Wa[k*8 + n - 776];
        __nv_bfloat16 h = __float2bfloat16(v);
        g_Bt1h[i] = h;
        g_Bt1l[i] = __float2bfloat16(v - __bfloat162float(h));
    } else if (i < N1ELEM + N2ELEM) {
        int j = i - N1ELEM;
        int n = j >> 8, k = j & 255;          // Bt2[n,k] = Wout[k,n]
        float v = Wout[k*512 + n];
        __nv_bfloat16 h = __float2bfloat16(v);
        g_Bt2h[j] = h;
        g_Bt2l[j] = __float2bfloat16(v - __bfloat162float(h));
    } else {
        int j = i - N1ELEM - N2ELEM;
        if (j < ACTF * NPU) {
            int r = j / NPU, c = j - r * NPU;
            float v;
            if (c < 256)      v = Wku[r*256 + c];
            else if (c < 512) v = Wvu[r*256 + c - 256];
            else              v = Wg[r*8 + c - 512];
            g_Wucat[j] = v;
        }
    }
}

// ---------------- 2. HMMA split-bf16 GEMM -----------------------------------
// C[M,N] = A[M,K](fp32) @ Bt[N,K]^T (split bf16), tile 128x128, BK=32.
#define ROWB 80                 // padded smem row stride (bytes) - conflict-free ldmatrix
#define OAH 0
#define OAL 10240
#define OBH 20480
#define OBL 30720
#define STG 40960
#define SMEM_TOTAL (2*STG)

__device__ __forceinline__ void gemm_hmma(const float* __restrict__ A,
                                          const __nv_bfloat16* __restrict__ Bh,
                                          const __nv_bfloat16* __restrict__ Bl,
                                          float* __restrict__ C,
                                          const float* __restrict__ bias,
                                          int N, int K) {
    extern __shared__ char smem[];
    uint32_t sb = smem_to_u32(smem);
    int tid = threadIdx.x, lane = tid & 31, wid = tid >> 5;
    int m0 = blockIdx.y * 128, n0 = blockIdx.x * 128;
    int wm = (wid >> 2) * 64, wn = (wid & 3) * 32;

    // per-lane ldmatrix byte offsets
    uint32_t aOff = (uint32_t)((wm + (lane & 7) + ((lane >> 3) & 1) * 8) * ROWB
                               + ((lane >> 4) * 8) * 2);
    uint32_t bOff = (uint32_t)((wn + (lane & 7) + ((lane >> 4) & 1) * 8) * ROWB
                               + (((lane >> 3) & 1) * 8) * 2);

    float acc[4][4][4];
#pragma unroll
    for (int mt = 0; mt < 4; mt++)
#pragma unroll
        for (int nt = 0; nt < 4; nt++)
#pragma unroll
            for (int e = 0; e < 4; e++) acc[mt][nt][e] = 0.f;

    const float* Ag = A + (size_t)m0 * K;
    const __nv_bfloat16* Bhg = Bh + (size_t)n0 * K;
    const __nv_bfloat16* Blg = Bl + (size_t)n0 * K;

    int nkc = K >> 5;
    float4 aR[4];
    uint4 bhR[2], blR[2];

    // indices for the global->smem path
    int arow = tid >> 3, ac4 = (tid & 7) << 2;     // + i*32 rows
    int bn = tid >> 2, bk8 = (tid & 3) << 3;       // + i*64 rows

    // prologue: load chunk 0
#pragma unroll
    for (int i = 0; i < 4; i++)
        aR[i] = *(const float4*)(Ag + (size_t)(arow + i * 32) * K + ac4);
#pragma unroll
    for (int i = 0; i < 2; i++) {
        bhR[i] = *(const uint4*)(Bhg + (size_t)(bn + i * 64) * K + bk8);
        blR[i] = *(const uint4*)(Blg + (size_t)(bn + i * 64) * K + bk8);
    }
    {
        char* st = smem;
#pragma unroll
        for (int i = 0; i < 4; i++) {
            uint2 hp, lp;
            hp.x = pack_bf16(aR[i].x, aR[i].y);
            hp.y = pack_bf16(aR[i].z, aR[i].w);
            lp.x = pack_bf16(aR[i].x - __bfloat162float(__float2bfloat16(aR[i].x)),
                             aR[i].y - __bfloat162float(__float2bfloat16(aR[i].y)));
            lp.y = pack_bf16(aR[i].z - __bfloat162float(__float2bfloat16(aR[i].z)),
                             aR[i].w - __bfloat162float(__float2bfloat16(aR[i].w)));
            *(uint2*)(st + OAH + (arow + i * 32) * ROWB + ac4 * 2) = hp;
            *(uint2*)(st + OAL + (arow + i * 32) * ROWB + ac4 * 2) = lp;
        }
#pragma unroll
        for (int i = 0; i < 2; i++) {
            *(uint4*)(st + OBH + (bn + i * 64) * ROWB + bk8 * 2) = bhR[i];
            *(uint4*)(st + OBL + (bn + i * 64) * ROWB + bk8 * 2) = blR[i];
        }
    }
    __syncthreads();

    for (int kc = 0; kc < nkc; kc++) {
        int s = kc & 1;
        bool more = (kc + 1 < nkc);
        if (more) {
            int ko = (kc + 1) * 32;
#pragma unroll
            for (int i = 0; i < 4; i++)
                aR[i] = *(const float4*)(Ag + (size_t)(arow + i * 32) * K + ko + ac4);
#pragma unroll
            for (int i = 0; i < 2; i++) {
                bhR[i] = *(const uint4*)(Bhg + (size_t)(bn + i * 64) * K + ko + bk8);
                blR[i] = *(const uint4*)(Blg + (size_t)(bn + i * 64) * K + ko + bk8);
            }
        }
        // compute on stage s
        uint32_t stb = sb + s * STG;
#pragma unroll
        for (int ks = 0; ks < 2; ks++) {
            uint32_t kb = ks * 32;
            uint32_t af[4][4], bhF[2][4], blF[2][4];
#pragma unroll
            for (int mt = 0; mt < 4; mt++)
                ldsm_x4(af[mt], stb + OAH + aOff + mt * (16 * ROWB) + kb);
#pragma unroll
            for (int np = 0; np < 2; np++) {
                ldsm_x4(bhF[np], stb + OBH + bOff + np * (16 * ROWB) + kb);
                ldsm_x4(blF[np], stb + OBL + bOff + np * (16 * ROWB) + kb);
            }
#pragma unroll
            for (int mt = 0; mt < 4; mt++)
#pragma unroll
                for (int nt = 0; nt < 4; nt++)
                    mma16816(acc[mt][nt], af[mt], &bhF[nt >> 1][(nt & 1) * 2]);
#pragma unroll
            for (int mt = 0; mt < 4; mt++)
#pragma unroll
                for (int nt = 0; nt < 4; nt++)
                    mma16816(acc[mt][nt], af[mt], &blF[nt >> 1][(nt & 1) * 2]);
            // reload A-lo into af, multiply by B-hi
#pragma unroll
            for (int mt = 0; mt < 4; mt++)
                ldsm_x4(af[mt], stb + OAL + aOff + mt * (16 * ROWB) + kb);
#pragma unroll
            for (int mt = 0; mt < 4; mt++)
#pragma unroll
                for (int nt = 0; nt < 4; nt++)
                    mma16816(acc[mt][nt], af[mt], &bhF[nt >> 1][(nt & 1) * 2]);
        }
        if (more) {
            __syncthreads();
            char* st = smem + ((kc + 1) & 1) * STG;
#pragma unroll
            for (int i = 0; i < 4; i++) {
                uint2 hp, lp;
                hp.x = pack_bf16(aR[i].x, aR[i].y);
                hp.y = pack_bf16(aR[i].z, aR[i].w);
                lp.x = pack_bf16(aR[i].x - __bfloat162float(__float2bfloat16(aR[i].x)),
                                 aR[i].y - __bfloat162float(__float2bfloat16(aR[i].y)));
                lp.y = pack_bf16(aR[i].z - __bfloat162float(__float2bfloat16(aR[i].z)),
                                 aR[i].w - __bfloat162float(__float2bfloat16(aR[i].w)));
                *(uint2*)(st + OAH + (arow + i * 32) * ROWB + ac4 * 2) = hp;
                *(uint2*)(st + OAL + (arow + i * 32) * ROWB + ac4 * 2) = lp;
            }
#pragma unroll
            for (int i = 0; i < 2; i++) {
                *(uint4*)(st + OBH + (bn + i * 64) * ROWB + bk8 * 2) = bhR[i];
                *(uint4*)(st + OBL + (bn + i * 64) * ROWB + bk8 * 2) = blR[i];
            }
            __syncthreads();
        }
    }

    // epilogue
#pragma unroll
    for (int mt = 0; mt < 4; mt++) {
        int r0 = m0 + wm + mt * 16 + (lane >> 2);
#pragma unroll
        for (int nt = 0; nt < 4; nt++) {
            int col = n0 + wn + nt * 8 + (lane & 3) * 2;
            float b0 = 0.f, b1 = 0.f;
            if (bias) { b0 = bias[col]; b1 = bias[col + 1]; }
            float2 v0, v1;
            v0.x = acc[mt][nt][0] + b0; v0.y = acc[mt][nt][1] + b1;
            v1.x = acc[mt][nt][2] + b0; v1.y = acc[mt][nt][3] + b1;
            *(float2*)(C + (size_t)r0 * N + col) = v0;
            *(float2*)(C + (size_t)(r0 + 8) * N + col) = v1;
        }
    }
}

__global__ __launch_bounds__(256) void gemm1_tc(const float* __restrict__ x) {
    gemm_hmma(x, g_Bt1h, g_Bt1l, g_proj, nullptr, NP1, NF);
}
__global__ __launch_bounds__(256) void gemm2_tc(const float* __restrict__ bout,
                                                float* __restrict__ y) {
    gemm_hmma(g_out, g_Bt2h, g_Bt2l, y, bout, NF, HID);
}

// ---------------- 3. action projection (K=16, tiny) ------------------------
__global__ __launch_bounds__(256) void action_proj(const float* __restrict__ act) {
    __shared__ float a[ACTF];
    int row = blockIdx.x;
    if (threadIdx.x < ACTF) a[threadIdx.x] = act[row * ACTF + threadIdx.x];
    __syncthreads();
    for (int c = threadIdx.x; c < NPU; c += blockDim.x) {
        float s = 0.f;
#pragma unroll
        for (int k = 0; k < ACTF; k++) s += a[k] * g_Wucat[k * NPU + c];
        g_projU[row * NPU + c] = s;
    }
}

// ---------------- 4. activations + l2norm + per-step scalars ----------------
__global__ __launch_bounds__(256) void act_kernel(const float* __restrict__ mask) {
    int w = (blockIdx.x * blockDim.x + threadIdx.x) >> 5;   // (b*S+s)*H + h
    int lane = threadIdx.x & 31;
    if (w >= ROWS * NH) return;
    int bs = w >> 3, h = w & 7;
    int pb = bs * NP1;
    float qr  = g_proj[pb + h*32 + lane];
    float kr  = g_proj[pb + 256 + h*32 + lane];
    float vr  = g_proj[pb + 512 + h*32 + lane];
    float kur = g_projU[bs*NPU + h*32 + lane];
    float vur = g_projU[bs*NPU + 256 + h*32 + lane];

    float q  = qr * sigm(qr);
    float k  = kr * sigm(kr);
    float ku = kur * sigm(kur);

    float sq = q*q, sk = k*k, sku = ku*ku;
#pragma unroll
    for (int o = 16; o > 0; o >>= 1) {
        sq  += __shfl_xor_sync(0xffffffffu, sq,  o);
        sk  += __shfl_xor_sync(0xffffffffu, sk,  o);
        sku += __shfl_xor_sync(0xffffffffu, sku, o);
    }
    q  *= rsqrtf(sq  + EPSF);
    k  *= rsqrtf(sk  + EPSF);
    ku *= rsqrtf(sku + EPSF);

    float dk = ku * k;
#pragma unroll
    for (int o = 16; o > 0; o >>= 1) dk += __shfl_xor_sync(0xffffffffu, dk, o);

    int base = w * 32;
    g_qn[base + lane]  = q;
    g_kn[base + lane]  = k;
    g_kun[base + lane] = ku;
    g_vs[base + lane]  = vr;
    g_vu[base + lane]  = vur;
    if (lane == 0) {
        float br = g_proj[pb + 768 + h];
        float ar = g_proj[pb + 776 + h];
        float gr = g_projU[bs*NPU + 512 + h];
        float m  = mask[bs];
        g_sc[w*4 + 0] = sigm(br);                 // beta
        g_sc[w*4 + 1] = sigm(ar) * (1.f - m);     // Aeff
        g_sc[w*4 + 2] = sigm(gr);                 // Bg
        g_sc[w*4 + 3] = dk;                       // ku . k
    }
}

// ---------------- 5. phase 1: chunked scan (warp per chain-chunk) ----------
__global__ __launch_bounds__(128) void phase1() {
    int wg = blockIdx.x * 4 + (threadIdx.x >> 5);   // 0..1023
    int lane = threadIdx.x & 31;
    int chain = wg >> 5;        // b*8+h
    int c = wg & 31;
    int b = chain >> 3, h = chain & 7;

    float cum[32], hl[32];
#pragma unroll
    for (int j = 0; j < 32; j++) { cum[j] = (j == lane) ? 1.f : 0.f; hl[j] = 0.f; }

    int t0 = c * CHUNK;
    for (int t = t0; t < t0 + CHUNK; t++) {
        int w = (b * NS + t) * NH + h;
        int base = w * 32;
        float kreg  = g_kn[base + lane];
        float qreg  = g_qn[base + lane];
        float kureg = g_kun[base + lane];
        float vs = g_vs[base + lane];
        float vu = g_vu[base + lane];
        float beta = g_sc[w*4 + 0];
        float Ae   = g_sc[w*4 + 1];
        float Bg   = g_sc[w*4 + 2];
        float kuk  = g_sc[w*4 + 3];

        float ck = 0.f, hk = 0.f;
#pragma unroll
        for (int j = 0; j < 32; j++) {
            float kj = __shfl_sync(0xffffffffu, kreg, j);
            ck += cum[j] * kj;
            hk += hl[j]  * kj;
        }
        float e  = Ae * beta * ck;
        float cc = beta * vs - Ae * beta * hk - Bg * beta * kuk * vu;
        float dd = Bg * vu;

        float u = 0.f, wv = 0.f;
#pragma unroll
        for (int j = 0; j < 32; j++) {
            float kj  = __shfl_sync(0xffffffffu, kreg,  j);
            float kuj = __shfl_sync(0xffffffffu, kureg, j);
            float qj  = __shfl_sync(0xffffffffu, qreg,  j);
            cum[j] = Ae * cum[j] - e * kj;
            hl[j]  = Ae * hl[j] + cc * kj + dd * kuj;
            u  += cum[j] * qj;
            wv += hl[j]  * qj;
        }
        g_u[base + lane] = u;
        g_w[base + lane] = wv;
    }
    int mb = (chain * NC + c) * 1024 + lane * 32;
#pragma unroll
    for (int j = 0; j < 32; j += 4) {
        *(float4*)&g_cum[mb + j] = make_float4(cum[j], cum[j+1], cum[j+2], cum[j+3]);
        *(float4*)&g_loc[mb + j] = make_float4(hl[j],  hl[j+1],  hl[j+2],  hl[j+3]);
    }
}

// ---------------- 6. phase 2: fold chunks -----------------------------------
__global__ __launch_bounds__(1024) void phase2(const float* __restrict__ carry,
                                               float* __restrict__ outCarry) {
    int chain = blockIdx.x;
    int i = threadIdx.x >> 5, j = threadIdx.x & 31;
    float hreg = carry[chain * 1024 + i * 32 + j];
    for (int c = 0; c < NC; c++) {
        int mb = (chain * NC + c) * 1024;
        g_hinit[mb + i * 32 + j] = hreg;       // state at chunk start
        float nv = g_loc[mb + i * 32 + j];
#pragma unroll
        for (int m = 0; m < 32; m++)
            nv += __shfl_sync(0xffffffffu, hreg, m) * g_cum[mb + m * 32 + j];
        hreg = nv;
    }
    outCarry[chain * 1024 + i * 32 + j] = hreg;  // new_carry
}

// ---------------- 7. phase 3: out_t = Hinit @ u_t + w_t ---------------------
__global__ __launch_bounds__(256) void phase3() {
    __shared__ float sh[32 * 33];
    int blk = blockIdx.x;            // chain*NC + c
    int chain = blk >> 5, c = blk & 31;
    int b = chain >> 3, h = chain & 7;
    int mb = blk * 1024;
    for (int idx = threadIdx.x; idx < 1024; idx += 256)
        sh[(idx >> 5) * 33 + (idx & 31)] = g_hinit[mb + idx];
    __syncthreads();
    int warp = threadIdx.x >> 5, lane = threadIdx.x & 31;
    for (int it = 0; it < 8; it++) {
        int t = c * CHUNK + it * 8 + warp;
        int w = (b * NS + t) * NH + h;
        int base = w * 32;
        float ul  = g_u[base + lane];
        float acc = g_w[base + lane];
#pragma unroll
        for (int j = 0; j < 32; j++)
            acc += sh[lane * 33 + j] * __shfl_sync(0xffffffffu, ul, j);
        g_out[(b * NS + t) * HID + h * 32 + lane] = acc;
    }
}

// ---------------- 8. RMS norm over 256 + scale ------------------------------
__global__ __launch_bounds__(256) void rms_kernel(const float* __restrict__ scale) {
    __shared__ float red[8];
    int bs = blockIdx.x;
    float v = g_out[bs * HID + threadIdx.x];
    float ss = v * v;
#pragma unroll
    for (int o = 16; o > 0; o >>= 1) ss += __shfl_xor_sync(0xffffffffu, ss, o);
    if ((threadIdx.x & 31) == 0) red[threadIdx.x >> 5] = ss;
    __syncthreads();
    float tot = 0.f;
#pragma unroll
    for (int r = 0; r < 8; r++) tot += red[r];
    float inv = rsqrtf(tot * (1.f / 256.f) + EPSF);
    g_out[bs * HID + threadIdx.x] = v * inv * scale[threadIdx.x];
}

// ---------------- launcher ---------------------------------------------------
extern "C" void kernel_launch(void* const* d_in, const int* in_sizes, int n_in,
                              void* d_out, int out_size) {
    const float* x      = (const float*)d_in[0];
    const float* action = (const float*)d_in[1];
    const float* mask   = (const float*)d_in[2];
    const float* carry  = (const float*)d_in[3];
    const float* Wq     = (const float*)d_in[4];
    const float* Wk     = (const float*)d_in[5];
    const float* Wv     = (const float*)d_in[6];
    const float* Wbeta  = (const float*)d_in[7];
    const float* Walpha = (const float*)d_in[8];
    const float* Wku    = (const float*)d_in[9];
    const float* Wvu    = (const float*)d_in[10];
    const float* Wgamma = (const float*)d_in[11];
    const float* rmssc  = (const float*)d_in[12];
    const float* Wout   = (const float*)d_in[13];
    const float* bout   = (const float*)d_in[14];

    float* outCarry = (float*)d_out;                       // (B,H,D,D) = 32768
    float* y        = (float*)d_out + NB * NH * ND * ND;   // (B,S,F)

    static bool attr_set = false;
    if (!attr_set) {
        cudaFuncSetAttribute(gemm1_tc, cudaFuncAttributeMaxDynamicSharedMemorySize, SMEM_TOTAL);
        cudaFuncSetAttribute(gemm2_tc, cudaFuncAttributeMaxDynamicSharedMemorySize, SMEM_TOTAL);
        attr_set = true;
    }

    int nprep = N1ELEM + N2ELEM + ACTF * NPU;
    prep_weights<<<(nprep + 255) / 256, 256>>>(Wq, Wk, Wv, Wbeta, Walpha, Wku, Wvu,
                                               Wgamma, Wout);

    dim3 g1(NP1 / 128, ROWS / 128);       // (7, 64)
    gemm1_tc<<<g1, 256, SMEM_TOTAL>>>(x);

    action_proj<<<ROWS, 256>>>(action);
    act_kernel<<<(ROWS * NH * 32) / 256, 256>>>(mask);

    phase1<<<256, 128>>>();
    phase2<<<32, 1024>>>(carry, outCarry);
    phase3<<<1024, 256>>>();
    rms_kernel<<<ROWS, 256>>>(rmssc);

    dim3 g2(NF / 128, ROWS / 128);        // (4, 64)
    gemm2_tc<<<g2, 256, SMEM_TOTAL>>>(bout, y);
}